// round 16
// baseline (speedup 1.0000x reference)
#include <cuda_runtime.h>
#include <cuda_bf16.h>
#include <cstdint>

#define TOK_TOTAL 65536
#define TOK_HALF  32768
#define HD 1024
#define NLEV 4
#define MAX_AMB 8192
#define AMB_THRESH 2e-2f

// ---------------------------------------------------------------------------
// Scratch (static device globals; no runtime allocation allowed)
// ---------------------------------------------------------------------------
__device__ float g_logits[TOK_TOTAL * NLEV];
__device__ int   g_idx[NLEV * TOK_TOTAL];
__device__ int   g_count[NLEV];
__device__ int   g_amb[MAX_AMB];
__device__ int   g_amb_count;

// Inputs pre-split to bf16 hi/lo (combined keys|values, token-major)
__device__ __align__(256) __nv_bfloat16 g_Xhi[(size_t)TOK_TOTAL * HD];
__device__ __align__(256) __nv_bfloat16 g_Xlo[(size_t)TOK_TOTAL * HD];

// Hidden activations, pre-split to bf16 hi/lo
__device__ __align__(256) __nv_bfloat16 g_Hhi[(size_t)TOK_TOTAL * HD];
__device__ __align__(256) __nv_bfloat16 g_Hlo[(size_t)TOK_TOTAL * HD];

// Transposed + bf16-split weights (K-major: row n, contiguous k)
#define WT_TOTAL 1966080   // sum over levels of d*1024
__device__ __align__(256) __nv_bfloat16 g_w1t_hi[WT_TOTAL], g_w1t_lo[WT_TOTAL];
__device__ __align__(256) __nv_bfloat16 g_w2t_hi[WT_TOTAL], g_w2t_lo[WT_TOTAL];
// Predictor W1 transposed (hi only — single-product predictor): [n][k]
__device__ __align__(256) __nv_bfloat16 g_pw1t_hi[HD * HD];

__device__ __forceinline__ size_t WOFF(int l) {
    return (l == 0) ? 0 : (l == 1) ? 1048576 : (l == 2) ? 1572864 : 1835008;
}

struct CompParams {
    const float* keys;
    const float* values;
    const float* w1[NLEV];
    const float* b1[NLEV];
    const float* w2[NLEV];
    const float* b2[NLEV];
    float* out;
};

// ---------------------------------------------------------------------------
// Low-level helpers
// ---------------------------------------------------------------------------
__device__ __forceinline__ uint32_t smem_to_u32(const void* p) {
    uint32_t a;
    asm("{ .reg .u64 t; cvta.to.shared.u64 t, %1; cvt.u32.u64 %0, t; }"
        : "=r"(a) : "l"(p));
    return a;
}
// 128-byte-row swizzle (predictor tiles)
#define SWZ(off)  ((off) ^ (((off) >> 3) & 0x70))
// 64-byte-row swizzle (compress tiles): unit ^= row bits [1:2]
#define SWZ32(off) ((off) ^ (((off) >> 3) & 0x30))

#define CP_ASYNC16(saddr, gptr) \
    asm volatile("cp.async.cg.shared.global [%0], [%1], 16;" \
        :: "r"((uint32_t)(saddr)), "l"(gptr) : "memory")
#define CP_COMMIT() asm volatile("cp.async.commit_group;" ::: "memory")
#define CP_WAIT1() asm volatile("cp.async.wait_group 1;" ::: "memory")

__device__ __forceinline__ void ldsm_x4(uint32_t (&r)[4], uint32_t addr) {
    asm volatile("ldmatrix.sync.aligned.m8n8.x4.shared.b16 {%0,%1,%2,%3}, [%4];"
        : "=r"(r[0]), "=r"(r[1]), "=r"(r[2]), "=r"(r[3]) : "r"(addr));
}
__device__ __forceinline__ void mma_bf16(float (&d)[4], const uint32_t (&a)[4],
                                         uint32_t b0, uint32_t b1) {
    asm volatile(
        "mma.sync.aligned.m16n8k16.row.col.f32.bf16.bf16.f32 "
        "{%0,%1,%2,%3}, {%4,%5,%6,%7}, {%8,%9}, {%0,%1,%2,%3};"
        : "+f"(d[0]), "+f"(d[1]), "+f"(d[2]), "+f"(d[3])
        : "r"(a[0]), "r"(a[1]), "r"(a[2]), "r"(a[3]), "r"(b0), "r"(b1));
}

// bf16 hi/lo split, packed as bf16x2 words (low half = lower index)
__device__ __forceinline__ uint32_t pack_split(float a, float b, uint32_t& lo_out) {
    __nv_bfloat16 ha = __float2bfloat16(a), hb = __float2bfloat16(b);
    float ra = a - __bfloat162float(ha);
    float rb = b - __bfloat162float(hb);
    __nv_bfloat16 la = __float2bfloat16(ra), lb = __float2bfloat16(rb);
    lo_out = ((uint32_t)__bfloat16_as_ushort(lb) << 16) | (uint32_t)__bfloat16_as_ushort(la);
    return ((uint32_t)__bfloat16_as_ushort(hb) << 16) | (uint32_t)__bfloat16_as_ushort(ha);
}

// ---------------------------------------------------------------------------
// Smem layouts.
// Compress (full split): K=32 chunks, 4 buffers x 8KB (Ahi,Alo,Bhi,Blo),
//   3 stages x 32KB = 96KB -> 2 CTAs/SM. 64-byte rows, SWZ32.
// Predictor (hi only):   K=64 chunks, 2 buffers x 16KB, 3 stages = 96KB.
// fp32 accum staging (128x132) overlays stages after the pipeline drains.
// ---------------------------------------------------------------------------
#define SM32_AHI   0
#define SM32_ALO   8192
#define SM32_BHI   16384
#define SM32_BLO   24576
#define STAGE32    32768
#define SMEM_FULL  (3 * STAGE32 + 1024)

#define SM_HI_A  0
#define SM_HI_B  16384
#define STAGE_HI 32768
#define SMEM_HI  (3 * STAGE_HI + 1024)

#define ACC_LD   132

// ---------------------------------------------------------------------------
// cp.async chunk loaders
// ---------------------------------------------------------------------------
// K=32 chunk: thread owns row r = tid>>1, half seg = tid&1 (32B = 2x16B).
__device__ __forceinline__ void load_full32(
    uint32_t sbase,
    const __nv_bfloat16* ah, const __nv_bfloat16* al,
    const __nv_bfloat16* bh, const __nv_bfloat16* bl,
    int r, int seg, int kc)
{
    const int ge = kc + seg * 16;
#pragma unroll
    for (int q = 0; q < 2; q++) {
        uint32_t off = SWZ32((uint32_t)(r * 64 + seg * 32 + q * 16));
        CP_ASYNC16(sbase + SM32_AHI + off, ah + ge + q * 8);
        CP_ASYNC16(sbase + SM32_ALO + off, al + ge + q * 8);
        CP_ASYNC16(sbase + SM32_BHI + off, bh + ge + q * 8);
        CP_ASYNC16(sbase + SM32_BLO + off, bl + ge + q * 8);
    }
}

// K=64 chunk (predictor): 128-byte rows.
__device__ __forceinline__ void load_hi(
    uint32_t sbase, const __nv_bfloat16* ah, const __nv_bfloat16* bh,
    int r, int seg, int kc)
{
    const int ge = kc + seg * 32;
#pragma unroll
    for (int q = 0; q < 4; q++) {
        uint32_t off = SWZ((uint32_t)(r * 128 + seg * 64 + q * 16));
        CP_ASYNC16(sbase + SM_HI_A + off, ah + ge + q * 8);
        CP_ASYNC16(sbase + SM_HI_B + off, bh + ge + q * 8);
    }
}

// ---------------------------------------------------------------------------
// MMA microkernels. Block tile 128x128, 8 warps (4m x 2n), warp 32m x 64n.
// acc[mt(2)][nt(8)][4].
// ---------------------------------------------------------------------------
// K=32 chunk, 3-product split, B loaded per-ng pair (low register pressure).
__device__ __forceinline__ void mma_chunk_full32(
    uint32_t sbase, int m_base, int n_base, int lane, float (*acc)[8][4])
{
    const uint32_t sAhi = sbase + SM32_AHI, sAlo = sbase + SM32_ALO;
    const uint32_t sBhi = sbase + SM32_BHI, sBlo = sbase + SM32_BLO;
#pragma unroll
    for (int ks = 0; ks < 2; ks++) {
        const int k0 = ks * 16;
        const uint32_t arow = (uint32_t)(m_base + (lane & 15));
        const uint32_t acolb = (uint32_t)((k0 + ((lane >> 4) << 3)) * 2);
        uint32_t ahi[2][4], alo[2][4];
#pragma unroll
        for (int mt = 0; mt < 2; mt++) {
            uint32_t off = SWZ32((arow + mt * 16) * 64 + acolb);
            ldsm_x4(ahi[mt], sAhi + off);
            ldsm_x4(alo[mt], sAlo + off);
        }
        const uint32_t brow = (uint32_t)((lane & 7) + ((lane >> 4) << 3));
        const uint32_t bcolb = (uint32_t)((k0 + (((lane >> 3) & 1) << 3)) * 2);
#pragma unroll
        for (int ng = 0; ng < 4; ng++) {
            uint32_t off = SWZ32((uint32_t)(n_base + ng * 16 + brow) * 64 + bcolb);
            uint32_t th[4], tl[4];
            ldsm_x4(th, sBhi + off);
            ldsm_x4(tl, sBlo + off);
#pragma unroll
            for (int half = 0; half < 2; half++) {
                const int nt = ng * 2 + half;
                uint32_t bh0 = th[half * 2], bh1 = th[half * 2 + 1];
                uint32_t bl0 = tl[half * 2], bl1 = tl[half * 2 + 1];
#pragma unroll
                for (int mt = 0; mt < 2; mt++) {
                    mma_bf16(acc[mt][nt], ahi[mt], bh0, bh1);
                    mma_bf16(acc[mt][nt], ahi[mt], bl0, bl1);
                    mma_bf16(acc[mt][nt], alo[mt], bh0, bh1);
                }
            }
        }
    }
}

// K=64 chunk, single product (predictor).
__device__ __forceinline__ void mma_chunk_hi(
    uint32_t sbase, int m_base, int n_base, int lane, float (*acc)[8][4])
{
    const uint32_t sA = sbase + SM_HI_A, sB = sbase + SM_HI_B;
#pragma unroll
    for (int ks = 0; ks < 4; ks++) {
        const int k0 = ks * 16;
        const uint32_t arow = (uint32_t)(m_base + (lane & 15));
        const uint32_t acol = (uint32_t)(k0 + ((lane >> 4) << 3));
        uint32_t a[2][4];
#pragma unroll
        for (int mt = 0; mt < 2; mt++) {
            uint32_t off = SWZ((arow + mt * 16) * 128 + acol * 2);
            ldsm_x4(a[mt], sA + off);
        }
        const uint32_t brow = (uint32_t)((lane & 7) + ((lane >> 4) << 3));
        const uint32_t bcol = (uint32_t)(k0 + (((lane >> 3) & 1) << 3));
        uint32_t b[8][2];
#pragma unroll
        for (int ng = 0; ng < 4; ng++) {
            uint32_t off = SWZ((uint32_t)(n_base + ng * 16 + brow) * 128 + bcol * 2);
            uint32_t t[4];
            ldsm_x4(t, sB + off);
            b[ng * 2][0] = t[0]; b[ng * 2][1] = t[1];
            b[ng * 2 + 1][0] = t[2]; b[ng * 2 + 1][1] = t[3];
        }
#pragma unroll
        for (int mt = 0; mt < 2; mt++)
#pragma unroll
            for (int nt = 0; nt < 8; nt++)
                mma_bf16(acc[mt][nt], a[mt], b[nt][0], b[nt][1]);
    }
}

// ---------------------------------------------------------------------------
// 3-stage pipelines, ONE syncthreads per chunk. Buffer written for chunk c+2
// held chunk c-1, complete by the top-of-iteration sync. Empty tail commits
// keep wait_group(1) counting sound.
// ---------------------------------------------------------------------------
__device__ __forceinline__ void pipe_full32(
    uint32_t abase,
    const __nv_bfloat16* ah, const __nv_bfloat16* al,
    const __nv_bfloat16* bh, const __nv_bfloat16* bl,
    int r, int seg, int K, int m_base, int n_base, int lane, float (*acc)[8][4])
{
    const int NC = K >> 5;
    load_full32(abase, ah, al, bh, bl, r, seg, 0);
    CP_COMMIT();
    if (NC > 1) load_full32(abase + STAGE32, ah, al, bh, bl, r, seg, 32);
    CP_COMMIT();
    for (int c = 0; c < NC; c++) {
        CP_WAIT1();
        __syncthreads();
        mma_chunk_full32(abase + (c % 3) * STAGE32, m_base, n_base, lane, acc);
        if (c + 2 < NC)
            load_full32(abase + ((c + 2) % 3) * STAGE32, ah, al, bh, bl,
                        r, seg, (c + 2) << 5);
        CP_COMMIT();
    }
    __syncthreads();   // protect smem before epilogue overlays it
}

__device__ __forceinline__ void pipe_hi(
    uint32_t abase, const __nv_bfloat16* ah, const __nv_bfloat16* bh,
    int r, int seg, int K, int m_base, int n_base, int lane, float (*acc)[8][4])
{
    const int NC = K >> 6;
    load_hi(abase, ah, bh, r, seg, 0);
    CP_COMMIT();
    if (NC > 1) load_hi(abase + STAGE_HI, ah, bh, r, seg, 64);
    CP_COMMIT();
    for (int c = 0; c < NC; c++) {
        CP_WAIT1();
        __syncthreads();
        mma_chunk_hi(abase + (c % 3) * STAGE_HI, m_base, n_base, lane, acc);
        if (c + 2 < NC)
            load_hi(abase + ((c + 2) % 3) * STAGE_HI, ah, bh, r, seg, (c + 2) << 6);
        CP_COMMIT();
    }
}

// Store accum tile to padded fp32 smem (for coalesced epilogues)
__device__ __forceinline__ void stage_acc(float* acc_s, int m_base, int n_base,
                                          int lane, float (*acc)[8][4]) {
#pragma unroll
    for (int mt = 0; mt < 2; mt++)
#pragma unroll
        for (int nt = 0; nt < 8; nt++) {
            int row = m_base + mt * 16 + (lane >> 2);
            int col = n_base + nt * 8 + ((lane & 3) << 1);
            float* p = acc_s + (size_t)row * ACC_LD + col;
            p[0] = acc[mt][nt][0];
            p[1] = acc[mt][nt][1];
            p[8 * ACC_LD] = acc[mt][nt][2];
            p[8 * ACC_LD + 1] = acc[mt][nt][3];
        }
}

// ---------------------------------------------------------------------------
__global__ void zero_kernel() {
    int i = blockIdx.x * 256 + threadIdx.x;
    if (i < TOK_TOTAL * NLEV) g_logits[i] = 0.f;
    if (i < NLEV) g_count[i] = 0;
    if (i == 0) g_amb_count = 0;
}

// ---------------------------------------------------------------------------
// Split X (keys|values) to bf16 hi/lo once.
// ---------------------------------------------------------------------------
__global__ void splitX_kernel(const float* __restrict__ keys,
                              const float* __restrict__ values) {
    size_t i = ((size_t)blockIdx.x * 256 + threadIdx.x) * 4;
    const size_t half = (size_t)TOK_HALF * HD;
    const float* src = (i < half) ? keys + i : values + (i - half);
    float4 v = *(const float4*)src;
    uint32_t l0, l1;
    uint32_t h0 = pack_split(v.x, v.y, l0);
    uint32_t h1 = pack_split(v.z, v.w, l1);
    *(uint2*)(g_Xhi + i) = make_uint2(h0, h1);
    *(uint2*)(g_Xlo + i) = make_uint2(l0, l1);
}

// ---------------------------------------------------------------------------
// Weight prep: transpose + bf16 hi/lo split (compress); hi-only for Pw1.
// ---------------------------------------------------------------------------
__global__ void prep_kernel(CompParams P, const float* __restrict__ Pw1) {
    int l = blockIdx.y;
    int d = HD >> l;
    size_t base = WOFF(l);
    int total = d * HD;
    for (int i = blockIdx.x * 256 + threadIdx.x; i < total; i += gridDim.x * 256) {
        int n = i / HD, k = i - n * HD;
        float v = P.w1[l][(size_t)k * d + n];
        __nv_bfloat16 h = __float2bfloat16(v);
        g_w1t_hi[base + i] = h;
        g_w1t_lo[base + i] = __float2bfloat16(v - __bfloat162float(h));
        int n2 = i / d, k2 = i - n2 * d;
        float v2 = P.w2[l][(size_t)k2 * HD + n2];
        __nv_bfloat16 h2 = __float2bfloat16(v2);
        g_w2t_hi[base + i] = h2;
        g_w2t_lo[base + i] = __float2bfloat16(v2 - __bfloat162float(h2));
    }
    for (int i = blockIdx.x * 256 + threadIdx.x; i < 256 * HD; i += gridDim.x * 256) {
        int k = i >> 8, j = i & 255;
        float v = Pw1[(size_t)l * HD * 256 + i];
        g_pw1t_hi[(size_t)(l * 256 + j) * HD + k] = __float2bfloat16(v);
    }
}

// ---------------------------------------------------------------------------
// Predictor GEMM (single bf16 product, 2 CTAs/SM): approx logits only; the
// detect/refine net below guarantees exact argmax.
// ---------------------------------------------------------------------------
__global__ __launch_bounds__(256, 2) void predictor_mma(
    const float* __restrict__ Pb1, const float* __restrict__ Pw2)
{
    extern __shared__ char smraw[];
    char* sm = (char*)(((uintptr_t)smraw + 1023u) & ~(uintptr_t)1023u);
    const uint32_t abase = smem_to_u32(sm);
    const int tid = threadIdx.x;
    const int lane = tid & 31, wid = tid >> 5;
    const int m_base = (wid >> 1) * 32, n_base = (wid & 1) * 64;

    const int n0 = blockIdx.x * 128;
    const int lev = blockIdx.x >> 1;
    const int tokbase = blockIdx.y * 128;

    const int r = tid >> 1, seg = tid & 1;
    const int tok = tokbase + r;
    const __nv_bfloat16* ah = g_Xhi + (size_t)tok * HD;
    const __nv_bfloat16* bh = g_pw1t_hi + (size_t)(n0 + r) * HD;

    float acc[2][8][4];
#pragma unroll
    for (int mt = 0; mt < 2; mt++)
#pragma unroll
        for (int nt = 0; nt < 8; nt++)
#pragma unroll
            for (int q = 0; q < 4; q++) acc[mt][nt][q] = 0.f;

    pipe_hi(abase, ah, bh, r, seg, HD, m_base, n_base, lane, acc);

    float b1v[8][2], w2v[8][2];
#pragma unroll
    for (int nt = 0; nt < 8; nt++) {
        int n = n0 + n_base + nt * 8 + ((lane & 3) << 1);
        b1v[nt][0] = Pb1[n];     b1v[nt][1] = Pb1[n + 1];
        w2v[nt][0] = Pw2[n];     w2v[nt][1] = Pw2[n + 1];
    }
#pragma unroll
    for (int mt = 0; mt < 2; mt++) {
        float s0 = 0.f, s1 = 0.f;
#pragma unroll
        for (int nt = 0; nt < 8; nt++) {
            s0 += fmaxf(acc[mt][nt][0] + b1v[nt][0], 0.f) * w2v[nt][0]
                + fmaxf(acc[mt][nt][1] + b1v[nt][1], 0.f) * w2v[nt][1];
            s1 += fmaxf(acc[mt][nt][2] + b1v[nt][0], 0.f) * w2v[nt][0]
                + fmaxf(acc[mt][nt][3] + b1v[nt][1], 0.f) * w2v[nt][1];
        }
        s0 += __shfl_xor_sync(0xffffffffu, s0, 1);
        s0 += __shfl_xor_sync(0xffffffffu, s0, 2);
        s1 += __shfl_xor_sync(0xffffffffu, s1, 1);
        s1 += __shfl_xor_sync(0xffffffffu, s1, 2);
        if ((lane & 3) == 0) {
            int row = m_base + mt * 16 + (lane >> 2);
            atomicAdd(&g_logits[(size_t)(tokbase + row) * NLEV + lev], s0);
            atomicAdd(&g_logits[(size_t)(tokbase + row + 8) * NLEV + lev], s1);
        }
    }
}

// ---------------------------------------------------------------------------
// Gap triage + exact refine + argmax
// ---------------------------------------------------------------------------
__global__ void detect_kernel(const float* __restrict__ Pb2) {
    int t = blockIdx.x * 256 + threadIdx.x;
    if (t >= TOK_TOTAL) return;
    float v0 = g_logits[t * NLEV + 0] + Pb2[0];
    float v1 = g_logits[t * NLEV + 1] + Pb2[1];
    float v2 = g_logits[t * NLEV + 2] + Pb2[2];
    float v3 = g_logits[t * NLEV + 3] + Pb2[3];
    float m1 = fmaxf(fmaxf(v0, v1), fmaxf(v2, v3));
    float s = -1e30f;
    s = (v0 < m1) ? fmaxf(s, v0) : s;
    s = (v1 < m1) ? fmaxf(s, v1) : s;
    s = (v2 < m1) ? fmaxf(s, v2) : s;
    s = (v3 < m1) ? fmaxf(s, v3) : s;
    int ties = (v0 == m1) + (v1 == m1) + (v2 == m1) + (v3 == m1);
    float gap = (ties > 1) ? 0.f : (m1 - s);
    if (gap < AMB_THRESH) {
        int p = atomicAdd(&g_amb_count, 1);
        if (p < MAX_AMB) g_amb[p] = t;
    }
}

__global__ void refine_kernel(const float* __restrict__ keys,
                              const float* __restrict__ values,
                              const float* __restrict__ Pw1,
                              const float* __restrict__ Pb1,
                              const float* __restrict__ Pw2) {
    int nAmb = g_amb_count; if (nAmb > MAX_AMB) nAmb = MAX_AMB;
    int i = blockIdx.x >> 2;
    if (i >= nAmb) return;
    int l = blockIdx.x & 3;
    int t = g_amb[i];
    __shared__ float xs[HD];
    __shared__ float red[128];
    const float* x = (t < TOK_HALF) ? keys + (size_t)t * HD
                                    : values + (size_t)(t - TOK_HALF) * HD;
    for (int k = threadIdx.x; k < HD; k += 128) xs[k] = x[k];
    __syncthreads();
    float part = 0.f;
#pragma unroll
    for (int jj = 0; jj < 2; jj++) {
        int j = threadIdx.x + jj * 128;
        float acc = Pb1[l * 256 + j];
        const float* w = Pw1 + (size_t)l * HD * 256 + j;
        for (int k = 0; k < HD; k++) acc = fmaf(xs[k], w[(size_t)k * 256], acc);
        part += fmaxf(acc, 0.f) * Pw2[l * 256 + j];
    }
    red[threadIdx.x] = part;
    __syncthreads();
    for (int s = 64; s > 0; s >>= 1) {
        if (threadIdx.x < s) red[threadIdx.x] += red[threadIdx.x + s];
        __syncthreads();
    }
    if (threadIdx.x == 0) g_logits[(size_t)t * NLEV + l] = red[0];
}

__global__ void argmax_kernel(const float* __restrict__ Pb2) {
    int t = blockIdx.x * 256 + threadIdx.x;
    if (t >= TOK_TOTAL) return;
    float best = g_logits[t * NLEV] + Pb2[0];
    int bl = 0;
#pragma unroll
    for (int l = 1; l < NLEV; l++) {
        float v = g_logits[t * NLEV + l] + Pb2[l];
        if (v > best) { best = v; bl = l; }
    }
    int p = atomicAdd(&g_count[bl], 1);
    g_idx[bl * TOK_TOTAL + p] = t;
}

// ---------------------------------------------------------------------------
// Stage A (HMMA, K=32 chunks, 2 CTAs/SM): H = relu(Xg@w1_l+b1_l) -> bf16 hi/lo
// ---------------------------------------------------------------------------
__global__ __launch_bounds__(256, 2) void stageA_mma(CompParams P) {
    const int lev = blockIdx.z;
    const int d = HD >> lev;
    const int n0 = blockIdx.x * 128;
    if (n0 >= d) return;
    const int cnt = g_count[lev];
    const int m0 = blockIdx.y * 128;
    if (m0 >= cnt) return;

    extern __shared__ char smraw[];
    char* sm = (char*)(((uintptr_t)smraw + 1023u) & ~(uintptr_t)1023u);
    const uint32_t abase = smem_to_u32(sm);
    float* acc_s = (float*)sm;
    const int tid = threadIdx.x;
    const int lane = tid & 31, wid = tid >> 5;
    const int m_base = (wid >> 1) * 32, n_base = (wid & 1) * 64;

    const int r = tid >> 1, seg = tid & 1;
    int rload = m0 + r; if (rload > cnt - 1) rload = cnt - 1;
    const int tgat = g_idx[lev * TOK_TOTAL + rload];
    const __nv_bfloat16* ah = g_Xhi + (size_t)tgat * HD;
    const __nv_bfloat16* al = g_Xlo + (size_t)tgat * HD;
    const __nv_bfloat16* bh = g_w1t_hi + WOFF(lev) + (size_t)(n0 + r) * HD;
    const __nv_bfloat16* bl = g_w1t_lo + WOFF(lev) + (size_t)(n0 + r) * HD;

    float acc[2][8][4];
#pragma unroll
    for (int mt = 0; mt < 2; mt++)
#pragma unroll
        for (int nt = 0; nt < 8; nt++)
#pragma unroll
            for (int q = 0; q < 4; q++) acc[mt][nt][q] = 0.f;

    pipe_full32(abase, ah, al, bh, bl, r, seg, HD, m_base, n_base, lane, acc);

    stage_acc(acc_s, m_base, n_base, lane, acc);
    __syncthreads();

    {
        const bool live = (m0 + r < cnt);
        int tok = 0;
        if (live) tok = g_idx[lev * TOK_TOTAL + m0 + r];
        const float* src = acc_s + (size_t)r * ACC_LD + seg * 64;
        const float* b1 = P.b1[lev] + n0 + seg * 64;
        if (live) {
            __nv_bfloat16* dh = g_Hhi + (size_t)tok * HD + n0 + seg * 64;
            __nv_bfloat16* dl = g_Hlo + (size_t)tok * HD + n0 + seg * 64;
#pragma unroll
            for (int q = 0; q < 8; q++) {
                float4 v0 = *(const float4*)(src + q * 8);
                float4 v1 = *(const float4*)(src + q * 8 + 4);
                uint32_t hv[4], lv[4];
                hv[0] = pack_split(fmaxf(v0.x + b1[q * 8 + 0], 0.f),
                                   fmaxf(v0.y + b1[q * 8 + 1], 0.f), lv[0]);
                hv[1] = pack_split(fmaxf(v0.z + b1[q * 8 + 2], 0.f),
                                   fmaxf(v0.w + b1[q * 8 + 3], 0.f), lv[1]);
                hv[2] = pack_split(fmaxf(v1.x + b1[q * 8 + 4], 0.f),
                                   fmaxf(v1.y + b1[q * 8 + 5], 0.f), lv[2]);
                hv[3] = pack_split(fmaxf(v1.z + b1[q * 8 + 6], 0.f),
                                   fmaxf(v1.w + b1[q * 8 + 7], 0.f), lv[3]);
                *(uint2*)(dh + q * 8)     = make_uint2(hv[0], hv[1]);
                *(uint2*)(dh + q * 8 + 4) = make_uint2(hv[2], hv[3]);
                *(uint2*)(dl + q * 8)     = make_uint2(lv[0], lv[1]);
                *(uint2*)(dl + q * 8 + 4) = make_uint2(lv[2], lv[3]);
            }
        }
    }
}

// ---------------------------------------------------------------------------
// Stage B (HMMA, K=32 chunks, 2 CTAs/SM): out = Hg @ w2_l + b2_l
// ---------------------------------------------------------------------------
__global__ __launch_bounds__(256, 2) void stageB_mma(CompParams P) {
    const int lev = blockIdx.z;
    const int d = HD >> lev;         // K dimension
    const int n0 = blockIdx.x * 128; // N = 1024
    const int cnt = g_count[lev];
    const int m0 = blockIdx.y * 128;
    if (m0 >= cnt) return;

    extern __shared__ char smraw[];
    char* sm = (char*)(((uintptr_t)smraw + 1023u) & ~(uintptr_t)1023u);
    const uint32_t abase = smem_to_u32(sm);
    float* acc_s = (float*)sm;
    const int tid = threadIdx.x;
    const int lane = tid & 31, wid = tid >> 5;
    const int m_base = (wid >> 1) * 32, n_base = (wid & 1) * 64;

    const int r = tid >> 1, seg = tid & 1;
    int rload = m0 + r; if (rload > cnt - 1) rload = cnt - 1;
    const int tgat = g_idx[lev * TOK_TOTAL + rload];
    const __nv_bfloat16* ah = g_Hhi + (size_t)tgat * HD;
    const __nv_bfloat16* al = g_Hlo + (size_t)tgat * HD;
    const __nv_bfloat16* bh = g_w2t_hi + WOFF(lev) + (size_t)(n0 + r) * d;
    const __nv_bfloat16* bl = g_w2t_lo + WOFF(lev) + (size_t)(n0 + r) * d;

    float acc[2][8][4];
#pragma unroll
    for (int mt = 0; mt < 2; mt++)
#pragma unroll
        for (int nt = 0; nt < 8; nt++)
#pragma unroll
            for (int q = 0; q < 4; q++) acc[mt][nt][q] = 0.f;

    pipe_full32(abase, ah, al, bh, bl, r, seg, d, m_base, n_base, lane, acc);

    stage_acc(acc_s, m_base, n_base, lane, acc);
    __syncthreads();

    {
        const bool live = (m0 + r < cnt);
        int tok = 0;
        if (live) tok = g_idx[lev * TOK_TOTAL + m0 + r];
        const float* src = acc_s + (size_t)r * ACC_LD + seg * 64;
        const float* b2 = P.b2[lev] + n0 + seg * 64;
        if (live) {
            float* dst = P.out + (size_t)tok * HD + n0 + seg * 64;
#pragma unroll
            for (int q = 0; q < 8; q++) {
                float4 v0 = *(const float4*)(src + q * 8);
                float4 v1 = *(const float4*)(src + q * 8 + 4);
                v0.x += b2[q * 8 + 0]; v0.y += b2[q * 8 + 1];
                v0.z += b2[q * 8 + 2]; v0.w += b2[q * 8 + 3];
                v1.x += b2[q * 8 + 4]; v1.y += b2[q * 8 + 5];
                v1.z += b2[q * 8 + 6]; v1.w += b2[q * 8 + 7];
                *(float4*)(dst + q * 8)     = v0;
                *(float4*)(dst + q * 8 + 4) = v1;
            }
        }
    }
}

// ---------------------------------------------------------------------------
extern "C" void kernel_launch(void* const* d_in, const int* in_sizes, int n_in,
                              void* d_out, int out_size) {
    const float* keys   = (const float*)d_in[0];
    const float* values = (const float*)d_in[1];
    const float* Pw1    = (const float*)d_in[2];
    const float* Pb1    = (const float*)d_in[3];
    const float* Pw2    = (const float*)d_in[4];
    const float* Pb2    = (const float*)d_in[5];

    CompParams P;
    P.keys = keys; P.values = values;
    for (int l = 0; l < 4; l++) {
        P.w1[l] = (const float*)d_in[6 + l * 4 + 0];
        P.b1[l] = (const float*)d_in[6 + l * 4 + 1];
        P.w2[l] = (const float*)d_in[6 + l * 4 + 2];
        P.b2[l] = (const float*)d_in[6 + l * 4 + 3];
    }
    P.out = (float*)d_out;

    cudaFuncSetAttribute(predictor_mma, cudaFuncAttributeMaxDynamicSharedMemorySize, SMEM_HI);
    cudaFuncSetAttribute(stageA_mma,    cudaFuncAttributeMaxDynamicSharedMemorySize, SMEM_FULL);
    cudaFuncSetAttribute(stageB_mma,    cudaFuncAttributeMaxDynamicSharedMemorySize, SMEM_FULL);

    zero_kernel<<<(TOK_TOTAL * NLEV + 255) / 256, 256>>>();

    splitX_kernel<<<TOK_TOTAL * (HD / 4) / 256, 256>>>(keys, values);

    dim3 wgrid(256, 4);
    prep_kernel<<<wgrid, 256>>>(P, Pw1);

    dim3 pgrid(8, 512);
    predictor_mma<<<pgrid, 256, SMEM_HI>>>(Pb1, Pw2);

    detect_kernel<<<TOK_TOTAL / 256, 256>>>(Pb2);
    refine_kernel<<<MAX_AMB * 4, 128>>>(keys, values, Pw1, Pb1, Pw2);
    argmax_kernel<<<TOK_TOTAL / 256, 256>>>(Pb2);

    dim3 cgrid(8, 512, 4);
    stageA_mma<<<cgrid, 256, SMEM_FULL>>>(P);
    stageB_mma<<<cgrid, 256, SMEM_FULL>>>(P);
}

// round 17
// speedup vs baseline: 1.0017x; 1.0017x over previous
#include <cuda_runtime.h>
#include <cuda_bf16.h>
#include <cstdint>

#define TOK_TOTAL 65536
#define TOK_HALF  32768
#define HD 1024
#define NLEV 4
#define MAX_AMB 8192
#define AMB_THRESH 2e-2f

// ---------------------------------------------------------------------------
// Scratch (static device globals; no runtime allocation allowed)
// ---------------------------------------------------------------------------
__device__ float g_logits[TOK_TOTAL * NLEV];
__device__ int   g_idx[NLEV * TOK_TOTAL];
__device__ int   g_count[NLEV];
__device__ int   g_amb[MAX_AMB];
__device__ int   g_amb_count;

// Inputs pre-split to bf16 hi/lo (combined keys|values, token-major)
__device__ __align__(256) __nv_bfloat16 g_Xhi[(size_t)TOK_TOTAL * HD];
__device__ __align__(256) __nv_bfloat16 g_Xlo[(size_t)TOK_TOTAL * HD];

// Hidden activations, pre-split to bf16 hi/lo
__device__ __align__(256) __nv_bfloat16 g_Hhi[(size_t)TOK_TOTAL * HD];
__device__ __align__(256) __nv_bfloat16 g_Hlo[(size_t)TOK_TOTAL * HD];

// Transposed + bf16-split weights (K-major: row n, contiguous k)
#define WT_TOTAL 1966080   // sum over levels of d*1024
__device__ __align__(256) __nv_bfloat16 g_w1t_hi[WT_TOTAL], g_w1t_lo[WT_TOTAL];
__device__ __align__(256) __nv_bfloat16 g_w2t_hi[WT_TOTAL], g_w2t_lo[WT_TOTAL];
// Predictor W1 transposed (hi only — single-product predictor): [n][k]
__device__ __align__(256) __nv_bfloat16 g_pw1t_hi[HD * HD];

__device__ __forceinline__ size_t WOFF(int l) {
    return (l == 0) ? 0 : (l == 1) ? 1048576 : (l == 2) ? 1572864 : 1835008;
}

struct CompParams {
    const float* keys;
    const float* values;
    const float* w1[NLEV];
    const float* b1[NLEV];
    const float* w2[NLEV];
    const float* b2[NLEV];
    float* out;
};

// ---------------------------------------------------------------------------
// Low-level helpers
// ---------------------------------------------------------------------------
__device__ __forceinline__ uint32_t smem_to_u32(const void* p) {
    uint32_t a;
    asm("{ .reg .u64 t; cvta.to.shared.u64 t, %1; cvt.u32.u64 %0, t; }"
        : "=r"(a) : "l"(p));
    return a;
}
// 128-byte-row swizzle (predictor tiles)
#define SWZ(off)  ((off) ^ (((off) >> 3) & 0x70))
// 64-byte-row swizzle (compress tiles): unit ^= row bits [1:2]
#define SWZ32(off) ((off) ^ (((off) >> 3) & 0x30))

#define CP_ASYNC16(saddr, gptr) \
    asm volatile("cp.async.cg.shared.global [%0], [%1], 16;" \
        :: "r"((uint32_t)(saddr)), "l"(gptr) : "memory")
#define CP_COMMIT() asm volatile("cp.async.commit_group;" ::: "memory")
#define CP_WAIT1() asm volatile("cp.async.wait_group 1;" ::: "memory")

__device__ __forceinline__ void ldsm_x4(uint32_t (&r)[4], uint32_t addr) {
    asm volatile("ldmatrix.sync.aligned.m8n8.x4.shared.b16 {%0,%1,%2,%3}, [%4];"
        : "=r"(r[0]), "=r"(r[1]), "=r"(r[2]), "=r"(r[3]) : "r"(addr));
}
__device__ __forceinline__ void mma_bf16(float (&d)[4], const uint32_t (&a)[4],
                                         uint32_t b0, uint32_t b1) {
    asm volatile(
        "mma.sync.aligned.m16n8k16.row.col.f32.bf16.bf16.f32 "
        "{%0,%1,%2,%3}, {%4,%5,%6,%7}, {%8,%9}, {%0,%1,%2,%3};"
        : "+f"(d[0]), "+f"(d[1]), "+f"(d[2]), "+f"(d[3])
        : "r"(a[0]), "r"(a[1]), "r"(a[2]), "r"(a[3]), "r"(b0), "r"(b1));
}

// bf16 hi/lo split, packed as bf16x2 words (low half = lower index)
__device__ __forceinline__ uint32_t pack_split(float a, float b, uint32_t& lo_out) {
    __nv_bfloat16 ha = __float2bfloat16(a), hb = __float2bfloat16(b);
    float ra = a - __bfloat162float(ha);
    float rb = b - __bfloat162float(hb);
    __nv_bfloat16 la = __float2bfloat16(ra), lb = __float2bfloat16(rb);
    lo_out = ((uint32_t)__bfloat16_as_ushort(lb) << 16) | (uint32_t)__bfloat16_as_ushort(la);
    return ((uint32_t)__bfloat16_as_ushort(hb) << 16) | (uint32_t)__bfloat16_as_ushort(ha);
}

// ---------------------------------------------------------------------------
// Smem layouts.
// Compress (full split): K=32 chunks, 4 buffers x 8KB (Ahi,Alo,Bhi,Blo),
//   3 stages x 32KB = 96KB -> 2 CTAs/SM. 64-byte rows, SWZ32.
// Predictor (hi only):   K=64 chunks, 2 buffers x 16KB, 3 stages = 96KB.
// fp32 accum staging (128x132) overlays stages after the pipeline drains.
// ---------------------------------------------------------------------------
#define SM32_AHI   0
#define SM32_ALO   8192
#define SM32_BHI   16384
#define SM32_BLO   24576
#define STAGE32    32768
#define SMEM_FULL  (3 * STAGE32 + 1024)

#define SM_HI_A  0
#define SM_HI_B  16384
#define STAGE_HI 32768
#define SMEM_HI  (3 * STAGE_HI + 1024)

#define ACC_LD   132

// ---------------------------------------------------------------------------
// cp.async chunk loaders
// ---------------------------------------------------------------------------
// K=32 chunk: thread owns row r = tid>>1, half seg = tid&1 (32B = 2x16B).
__device__ __forceinline__ void load_full32(
    uint32_t sbase,
    const __nv_bfloat16* ah, const __nv_bfloat16* al,
    const __nv_bfloat16* bh, const __nv_bfloat16* bl,
    int r, int seg, int kc)
{
    const int ge = kc + seg * 16;
#pragma unroll
    for (int q = 0; q < 2; q++) {
        uint32_t off = SWZ32((uint32_t)(r * 64 + seg * 32 + q * 16));
        CP_ASYNC16(sbase + SM32_AHI + off, ah + ge + q * 8);
        CP_ASYNC16(sbase + SM32_ALO + off, al + ge + q * 8);
        CP_ASYNC16(sbase + SM32_BHI + off, bh + ge + q * 8);
        CP_ASYNC16(sbase + SM32_BLO + off, bl + ge + q * 8);
    }
}

// K=64 chunk (predictor): 128-byte rows.
__device__ __forceinline__ void load_hi(
    uint32_t sbase, const __nv_bfloat16* ah, const __nv_bfloat16* bh,
    int r, int seg, int kc)
{
    const int ge = kc + seg * 32;
#pragma unroll
    for (int q = 0; q < 4; q++) {
        uint32_t off = SWZ((uint32_t)(r * 128 + seg * 64 + q * 16));
        CP_ASYNC16(sbase + SM_HI_A + off, ah + ge + q * 8);
        CP_ASYNC16(sbase + SM_HI_B + off, bh + ge + q * 8);
    }
}

// ---------------------------------------------------------------------------
// MMA microkernels. Block tile 128x128, 8 warps (4m x 2n), warp 32m x 64n.
// acc[mt(2)][nt(8)][4].
// ---------------------------------------------------------------------------
// K=32 chunk, 3-product split, B loaded per-ng pair (low register pressure).
__device__ __forceinline__ void mma_chunk_full32(
    uint32_t sbase, int m_base, int n_base, int lane, float (*acc)[8][4])
{
    const uint32_t sAhi = sbase + SM32_AHI, sAlo = sbase + SM32_ALO;
    const uint32_t sBhi = sbase + SM32_BHI, sBlo = sbase + SM32_BLO;
#pragma unroll
    for (int ks = 0; ks < 2; ks++) {
        const int k0 = ks * 16;
        const uint32_t arow = (uint32_t)(m_base + (lane & 15));
        const uint32_t acolb = (uint32_t)((k0 + ((lane >> 4) << 3)) * 2);
        uint32_t ahi[2][4], alo[2][4];
#pragma unroll
        for (int mt = 0; mt < 2; mt++) {
            uint32_t off = SWZ32((arow + mt * 16) * 64 + acolb);
            ldsm_x4(ahi[mt], sAhi + off);
            ldsm_x4(alo[mt], sAlo + off);
        }
        const uint32_t brow = (uint32_t)((lane & 7) + ((lane >> 4) << 3));
        const uint32_t bcolb = (uint32_t)((k0 + (((lane >> 3) & 1) << 3)) * 2);
#pragma unroll
        for (int ng = 0; ng < 4; ng++) {
            uint32_t off = SWZ32((uint32_t)(n_base + ng * 16 + brow) * 64 + bcolb);
            uint32_t th[4], tl[4];
            ldsm_x4(th, sBhi + off);
            ldsm_x4(tl, sBlo + off);
#pragma unroll
            for (int half = 0; half < 2; half++) {
                const int nt = ng * 2 + half;
                uint32_t bh0 = th[half * 2], bh1 = th[half * 2 + 1];
                uint32_t bl0 = tl[half * 2], bl1 = tl[half * 2 + 1];
#pragma unroll
                for (int mt = 0; mt < 2; mt++) {
                    mma_bf16(acc[mt][nt], ahi[mt], bh0, bh1);
                    mma_bf16(acc[mt][nt], ahi[mt], bl0, bl1);
                    mma_bf16(acc[mt][nt], alo[mt], bh0, bh1);
                }
            }
        }
    }
}

// K=64 chunk, single product (predictor).
__device__ __forceinline__ void mma_chunk_hi(
    uint32_t sbase, int m_base, int n_base, int lane, float (*acc)[8][4])
{
    const uint32_t sA = sbase + SM_HI_A, sB = sbase + SM_HI_B;
#pragma unroll
    for (int ks = 0; ks < 4; ks++) {
        const int k0 = ks * 16;
        const uint32_t arow = (uint32_t)(m_base + (lane & 15));
        const uint32_t acol = (uint32_t)(k0 + ((lane >> 4) << 3));
        uint32_t a[2][4];
#pragma unroll
        for (int mt = 0; mt < 2; mt++) {
            uint32_t off = SWZ((arow + mt * 16) * 128 + acol * 2);
            ldsm_x4(a[mt], sA + off);
        }
        const uint32_t brow = (uint32_t)((lane & 7) + ((lane >> 4) << 3));
        const uint32_t bcol = (uint32_t)(k0 + (((lane >> 3) & 1) << 3));
        uint32_t b[8][2];
#pragma unroll
        for (int ng = 0; ng < 4; ng++) {
            uint32_t off = SWZ((uint32_t)(n_base + ng * 16 + brow) * 128 + bcol * 2);
            uint32_t t[4];
            ldsm_x4(t, sB + off);
            b[ng * 2][0] = t[0]; b[ng * 2][1] = t[1];
            b[ng * 2 + 1][0] = t[2]; b[ng * 2 + 1][1] = t[3];
        }
#pragma unroll
        for (int mt = 0; mt < 2; mt++)
#pragma unroll
            for (int nt = 0; nt < 8; nt++)
                mma_bf16(acc[mt][nt], a[mt], b[nt][0], b[nt][1]);
    }
}

// ---------------------------------------------------------------------------
// 3-stage pipelines, ONE syncthreads per chunk. Buffer written for chunk c+2
// held chunk c-1, complete by the top-of-iteration sync. Empty tail commits
// keep wait_group(1) counting sound.
// ---------------------------------------------------------------------------
__device__ __forceinline__ void pipe_full32(
    uint32_t abase,
    const __nv_bfloat16* ah, const __nv_bfloat16* al,
    const __nv_bfloat16* bh, const __nv_bfloat16* bl,
    int r, int seg, int K, int m_base, int n_base, int lane, float (*acc)[8][4])
{
    const int NC = K >> 5;
    load_full32(abase, ah, al, bh, bl, r, seg, 0);
    CP_COMMIT();
    if (NC > 1) load_full32(abase + STAGE32, ah, al, bh, bl, r, seg, 32);
    CP_COMMIT();
    for (int c = 0; c < NC; c++) {
        CP_WAIT1();
        __syncthreads();
        mma_chunk_full32(abase + (c % 3) * STAGE32, m_base, n_base, lane, acc);
        if (c + 2 < NC)
            load_full32(abase + ((c + 2) % 3) * STAGE32, ah, al, bh, bl,
                        r, seg, (c + 2) << 5);
        CP_COMMIT();
    }
    __syncthreads();   // protect smem before epilogue overlays it
}

__device__ __forceinline__ void pipe_hi(
    uint32_t abase, const __nv_bfloat16* ah, const __nv_bfloat16* bh,
    int r, int seg, int K, int m_base, int n_base, int lane, float (*acc)[8][4])
{
    const int NC = K >> 6;
    load_hi(abase, ah, bh, r, seg, 0);
    CP_COMMIT();
    if (NC > 1) load_hi(abase + STAGE_HI, ah, bh, r, seg, 64);
    CP_COMMIT();
    for (int c = 0; c < NC; c++) {
        CP_WAIT1();
        __syncthreads();
        mma_chunk_hi(abase + (c % 3) * STAGE_HI, m_base, n_base, lane, acc);
        if (c + 2 < NC)
            load_hi(abase + ((c + 2) % 3) * STAGE_HI, ah, bh, r, seg, (c + 2) << 6);
        CP_COMMIT();
    }
}

// Store accum tile to padded fp32 smem (for coalesced epilogues)
__device__ __forceinline__ void stage_acc(float* acc_s, int m_base, int n_base,
                                          int lane, float (*acc)[8][4]) {
#pragma unroll
    for (int mt = 0; mt < 2; mt++)
#pragma unroll
        for (int nt = 0; nt < 8; nt++) {
            int row = m_base + mt * 16 + (lane >> 2);
            int col = n_base + nt * 8 + ((lane & 3) << 1);
            float* p = acc_s + (size_t)row * ACC_LD + col;
            p[0] = acc[mt][nt][0];
            p[1] = acc[mt][nt][1];
            p[8 * ACC_LD] = acc[mt][nt][2];
            p[8 * ACC_LD + 1] = acc[mt][nt][3];
        }
}

// ---------------------------------------------------------------------------
__global__ void zero_kernel() {
    int i = blockIdx.x * 256 + threadIdx.x;
    if (i < TOK_TOTAL * NLEV) g_logits[i] = 0.f;
    if (i < NLEV) g_count[i] = 0;
    if (i == 0) g_amb_count = 0;
}

// ---------------------------------------------------------------------------
// Split X (keys|values) to bf16 hi/lo once.
// ---------------------------------------------------------------------------
__global__ void splitX_kernel(const float* __restrict__ keys,
                              const float* __restrict__ values) {
    size_t i = ((size_t)blockIdx.x * 256 + threadIdx.x) * 4;
    const size_t half = (size_t)TOK_HALF * HD;
    const float* src = (i < half) ? keys + i : values + (i - half);
    float4 v = *(const float4*)src;
    uint32_t l0, l1;
    uint32_t h0 = pack_split(v.x, v.y, l0);
    uint32_t h1 = pack_split(v.z, v.w, l1);
    *(uint2*)(g_Xhi + i) = make_uint2(h0, h1);
    *(uint2*)(g_Xlo + i) = make_uint2(l0, l1);
}

// ---------------------------------------------------------------------------
// Weight prep: transpose + bf16 hi/lo split (compress); hi-only for Pw1.
// ---------------------------------------------------------------------------
__global__ void prep_kernel(CompParams P, const float* __restrict__ Pw1) {
    int l = blockIdx.y;
    int d = HD >> l;
    size_t base = WOFF(l);
    int total = d * HD;
    for (int i = blockIdx.x * 256 + threadIdx.x; i < total; i += gridDim.x * 256) {
        int n = i / HD, k = i - n * HD;
        float v = P.w1[l][(size_t)k * d + n];
        __nv_bfloat16 h = __float2bfloat16(v);
        g_w1t_hi[base + i] = h;
        g_w1t_lo[base + i] = __float2bfloat16(v - __bfloat162float(h));
        int n2 = i / d, k2 = i - n2 * d;
        float v2 = P.w2[l][(size_t)k2 * HD + n2];
        __nv_bfloat16 h2 = __float2bfloat16(v2);
        g_w2t_hi[base + i] = h2;
        g_w2t_lo[base + i] = __float2bfloat16(v2 - __bfloat162float(h2));
    }
    for (int i = blockIdx.x * 256 + threadIdx.x; i < 256 * HD; i += gridDim.x * 256) {
        int k = i >> 8, j = i & 255;
        float v = Pw1[(size_t)l * HD * 256 + i];
        g_pw1t_hi[(size_t)(l * 256 + j) * HD + k] = __float2bfloat16(v);
    }
}

// ---------------------------------------------------------------------------
// Predictor GEMM (single bf16 product, 2 CTAs/SM): approx logits only; the
// detect/refine net below guarantees exact argmax.
// ---------------------------------------------------------------------------
__global__ __launch_bounds__(256, 2) void predictor_mma(
    const float* __restrict__ Pb1, const float* __restrict__ Pw2)
{
    extern __shared__ char smraw[];
    char* sm = (char*)(((uintptr_t)smraw + 1023u) & ~(uintptr_t)1023u);
    const uint32_t abase = smem_to_u32(sm);
    const int tid = threadIdx.x;
    const int lane = tid & 31, wid = tid >> 5;
    const int m_base = (wid >> 1) * 32, n_base = (wid & 1) * 64;

    const int n0 = blockIdx.x * 128;
    const int lev = blockIdx.x >> 1;
    const int tokbase = blockIdx.y * 128;

    const int r = tid >> 1, seg = tid & 1;
    const int tok = tokbase + r;
    const __nv_bfloat16* ah = g_Xhi + (size_t)tok * HD;
    const __nv_bfloat16* bh = g_pw1t_hi + (size_t)(n0 + r) * HD;

    float acc[2][8][4];
#pragma unroll
    for (int mt = 0; mt < 2; mt++)
#pragma unroll
        for (int nt = 0; nt < 8; nt++)
#pragma unroll
            for (int q = 0; q < 4; q++) acc[mt][nt][q] = 0.f;

    pipe_hi(abase, ah, bh, r, seg, HD, m_base, n_base, lane, acc);

    float b1v[8][2], w2v[8][2];
#pragma unroll
    for (int nt = 0; nt < 8; nt++) {
        int n = n0 + n_base + nt * 8 + ((lane & 3) << 1);
        b1v[nt][0] = Pb1[n];     b1v[nt][1] = Pb1[n + 1];
        w2v[nt][0] = Pw2[n];     w2v[nt][1] = Pw2[n + 1];
    }
#pragma unroll
    for (int mt = 0; mt < 2; mt++) {
        float s0 = 0.f, s1 = 0.f;
#pragma unroll
        for (int nt = 0; nt < 8; nt++) {
            s0 += fmaxf(acc[mt][nt][0] + b1v[nt][0], 0.f) * w2v[nt][0]
                + fmaxf(acc[mt][nt][1] + b1v[nt][1], 0.f) * w2v[nt][1];
            s1 += fmaxf(acc[mt][nt][2] + b1v[nt][0], 0.f) * w2v[nt][0]
                + fmaxf(acc[mt][nt][3] + b1v[nt][1], 0.f) * w2v[nt][1];
        }
        s0 += __shfl_xor_sync(0xffffffffu, s0, 1);
        s0 += __shfl_xor_sync(0xffffffffu, s0, 2);
        s1 += __shfl_xor_sync(0xffffffffu, s1, 1);
        s1 += __shfl_xor_sync(0xffffffffu, s1, 2);
        if ((lane & 3) == 0) {
            int row = m_base + mt * 16 + (lane >> 2);
            atomicAdd(&g_logits[(size_t)(tokbase + row) * NLEV + lev], s0);
            atomicAdd(&g_logits[(size_t)(tokbase + row + 8) * NLEV + lev], s1);
        }
    }
}

// ---------------------------------------------------------------------------
// Gap triage + exact refine + argmax
// ---------------------------------------------------------------------------
__global__ void detect_kernel(const float* __restrict__ Pb2) {
    int t = blockIdx.x * 256 + threadIdx.x;
    if (t >= TOK_TOTAL) return;
    float v0 = g_logits[t * NLEV + 0] + Pb2[0];
    float v1 = g_logits[t * NLEV + 1] + Pb2[1];
    float v2 = g_logits[t * NLEV + 2] + Pb2[2];
    float v3 = g_logits[t * NLEV + 3] + Pb2[3];
    float m1 = fmaxf(fmaxf(v0, v1), fmaxf(v2, v3));
    float s = -1e30f;
    s = (v0 < m1) ? fmaxf(s, v0) : s;
    s = (v1 < m1) ? fmaxf(s, v1) : s;
    s = (v2 < m1) ? fmaxf(s, v2) : s;
    s = (v3 < m1) ? fmaxf(s, v3) : s;
    int ties = (v0 == m1) + (v1 == m1) + (v2 == m1) + (v3 == m1);
    float gap = (ties > 1) ? 0.f : (m1 - s);
    if (gap < AMB_THRESH) {
        int p = atomicAdd(&g_amb_count, 1);
        if (p < MAX_AMB) g_amb[p] = t;
    }
}

__global__ void refine_kernel(const float* __restrict__ keys,
                              const float* __restrict__ values,
                              const float* __restrict__ Pw1,
                              const float* __restrict__ Pb1,
                              const float* __restrict__ Pw2) {
    int nAmb = g_amb_count; if (nAmb > MAX_AMB) nAmb = MAX_AMB;
    int i = blockIdx.x >> 2;
    if (i >= nAmb) return;
    int l = blockIdx.x & 3;
    int t = g_amb[i];
    __shared__ float xs[HD];
    __shared__ float red[128];
    const float* x = (t < TOK_HALF) ? keys + (size_t)t * HD
                                    : values + (size_t)(t - TOK_HALF) * HD;
    for (int k = threadIdx.x; k < HD; k += 128) xs[k] = x[k];
    __syncthreads();
    float part = 0.f;
#pragma unroll
    for (int jj = 0; jj < 2; jj++) {
        int j = threadIdx.x + jj * 128;
        float acc = Pb1[l * 256 + j];
        const float* w = Pw1 + (size_t)l * HD * 256 + j;
        for (int k = 0; k < HD; k++) acc = fmaf(xs[k], w[(size_t)k * 256], acc);
        part += fmaxf(acc, 0.f) * Pw2[l * 256 + j];
    }
    red[threadIdx.x] = part;
    __syncthreads();
    for (int s = 64; s > 0; s >>= 1) {
        if (threadIdx.x < s) red[threadIdx.x] += red[threadIdx.x + s];
        __syncthreads();
    }
    if (threadIdx.x == 0) g_logits[(size_t)t * NLEV + l] = red[0];
}

__global__ void argmax_kernel(const float* __restrict__ Pb2) {
    int t = blockIdx.x * 256 + threadIdx.x;
    if (t >= TOK_TOTAL) return;
    float best = g_logits[t * NLEV] + Pb2[0];
    int bl = 0;
#pragma unroll
    for (int l = 1; l < NLEV; l++) {
        float v = g_logits[t * NLEV + l] + Pb2[l];
        if (v > best) { best = v; bl = l; }
    }
    int p = atomicAdd(&g_count[bl], 1);
    g_idx[bl * TOK_TOTAL + p] = t;
}

// ---------------------------------------------------------------------------
// Stage A (HMMA, K=32 chunks, 2 CTAs/SM): H = relu(Xg@w1_l+b1_l) -> bf16 hi/lo
// ---------------------------------------------------------------------------
__global__ __launch_bounds__(256, 2) void stageA_mma(CompParams P) {
    const int lev = blockIdx.z;
    const int d = HD >> lev;
    const int n0 = blockIdx.x * 128;
    if (n0 >= d) return;
    const int cnt = g_count[lev];
    const int m0 = blockIdx.y * 128;
    if (m0 >= cnt) return;

    extern __shared__ char smraw[];
    char* sm = (char*)(((uintptr_t)smraw + 1023u) & ~(uintptr_t)1023u);
    const uint32_t abase = smem_to_u32(sm);
    float* acc_s = (float*)sm;
    const int tid = threadIdx.x;
    const int lane = tid & 31, wid = tid >> 5;
    const int m_base = (wid >> 1) * 32, n_base = (wid & 1) * 64;

    const int r = tid >> 1, seg = tid & 1;
    int rload = m0 + r; if (rload > cnt - 1) rload = cnt - 1;
    const int tgat = g_idx[lev * TOK_TOTAL + rload];
    const __nv_bfloat16* ah = g_Xhi + (size_t)tgat * HD;
    const __nv_bfloat16* al = g_Xlo + (size_t)tgat * HD;
    const __nv_bfloat16* bh = g_w1t_hi + WOFF(lev) + (size_t)(n0 + r) * HD;
    const __nv_bfloat16* bl = g_w1t_lo + WOFF(lev) + (size_t)(n0 + r) * HD;

    float acc[2][8][4];
#pragma unroll
    for (int mt = 0; mt < 2; mt++)
#pragma unroll
        for (int nt = 0; nt < 8; nt++)
#pragma unroll
            for (int q = 0; q < 4; q++) acc[mt][nt][q] = 0.f;

    pipe_full32(abase, ah, al, bh, bl, r, seg, HD, m_base, n_base, lane, acc);

    stage_acc(acc_s, m_base, n_base, lane, acc);
    __syncthreads();

    {
        const bool live = (m0 + r < cnt);
        int tok = 0;
        if (live) tok = g_idx[lev * TOK_TOTAL + m0 + r];
        const float* src = acc_s + (size_t)r * ACC_LD + seg * 64;
        const float* b1 = P.b1[lev] + n0 + seg * 64;
        if (live) {
            __nv_bfloat16* dh = g_Hhi + (size_t)tok * HD + n0 + seg * 64;
            __nv_bfloat16* dl = g_Hlo + (size_t)tok * HD + n0 + seg * 64;
#pragma unroll
            for (int q = 0; q < 8; q++) {
                float4 v0 = *(const float4*)(src + q * 8);
                float4 v1 = *(const float4*)(src + q * 8 + 4);
                uint32_t hv[4], lv[4];
                hv[0] = pack_split(fmaxf(v0.x + b1[q * 8 + 0], 0.f),
                                   fmaxf(v0.y + b1[q * 8 + 1], 0.f), lv[0]);
                hv[1] = pack_split(fmaxf(v0.z + b1[q * 8 + 2], 0.f),
                                   fmaxf(v0.w + b1[q * 8 + 3], 0.f), lv[1]);
                hv[2] = pack_split(fmaxf(v1.x + b1[q * 8 + 4], 0.f),
                                   fmaxf(v1.y + b1[q * 8 + 5], 0.f), lv[2]);
                hv[3] = pack_split(fmaxf(v1.z + b1[q * 8 + 6], 0.f),
                                   fmaxf(v1.w + b1[q * 8 + 7], 0.f), lv[3]);
                *(uint2*)(dh + q * 8)     = make_uint2(hv[0], hv[1]);
                *(uint2*)(dh + q * 8 + 4) = make_uint2(hv[2], hv[3]);
                *(uint2*)(dl + q * 8)     = make_uint2(lv[0], lv[1]);
                *(uint2*)(dl + q * 8 + 4) = make_uint2(lv[2], lv[3]);
            }
        }
    }
}

// ---------------------------------------------------------------------------
// Stage B (HMMA, K=32 chunks, 2 CTAs/SM): out = Hg @ w2_l + b2_l
// ---------------------------------------------------------------------------
__global__ __launch_bounds__(256, 2) void stageB_mma(CompParams P) {
    const int lev = blockIdx.z;
    const int d = HD >> lev;         // K dimension
    const int n0 = blockIdx.x * 128; // N = 1024
    const int cnt = g_count[lev];
    const int m0 = blockIdx.y * 128;
    if (m0 >= cnt) return;

    extern __shared__ char smraw[];
    char* sm = (char*)(((uintptr_t)smraw + 1023u) & ~(uintptr_t)1023u);
    const uint32_t abase = smem_to_u32(sm);
    float* acc_s = (float*)sm;
    const int tid = threadIdx.x;
    const int lane = tid & 31, wid = tid >> 5;
    const int m_base = (wid >> 1) * 32, n_base = (wid & 1) * 64;

    const int r = tid >> 1, seg = tid & 1;
    int rload = m0 + r; if (rload > cnt - 1) rload = cnt - 1;
    const int tgat = g_idx[lev * TOK_TOTAL + rload];
    const __nv_bfloat16* ah = g_Hhi + (size_t)tgat * HD;
    const __nv_bfloat16* al = g_Hlo + (size_t)tgat * HD;
    const __nv_bfloat16* bh = g_w2t_hi + WOFF(lev) + (size_t)(n0 + r) * d;
    const __nv_bfloat16* bl = g_w2t_lo + WOFF(lev) + (size_t)(n0 + r) * d;

    float acc[2][8][4];
#pragma unroll
    for (int mt = 0; mt < 2; mt++)
#pragma unroll
        for (int nt = 0; nt < 8; nt++)
#pragma unroll
            for (int q = 0; q < 4; q++) acc[mt][nt][q] = 0.f;

    pipe_full32(abase, ah, al, bh, bl, r, seg, d, m_base, n_base, lane, acc);

    stage_acc(acc_s, m_base, n_base, lane, acc);
    __syncthreads();

    {
        const bool live = (m0 + r < cnt);
        int tok = 0;
        if (live) tok = g_idx[lev * TOK_TOTAL + m0 + r];
        const float* src = acc_s + (size_t)r * ACC_LD + seg * 64;
        const float* b2 = P.b2[lev] + n0 + seg * 64;
        if (live) {
            float* dst = P.out + (size_t)tok * HD + n0 + seg * 64;
#pragma unroll
            for (int q = 0; q < 8; q++) {
                float4 v0 = *(const float4*)(src + q * 8);
                float4 v1 = *(const float4*)(src + q * 8 + 4);
                v0.x += b2[q * 8 + 0]; v0.y += b2[q * 8 + 1];
                v0.z += b2[q * 8 + 2]; v0.w += b2[q * 8 + 3];
                v1.x += b2[q * 8 + 4]; v1.y += b2[q * 8 + 5];
                v1.z += b2[q * 8 + 6]; v1.w += b2[q * 8 + 7];
                *(float4*)(dst + q * 8)     = v0;
                *(float4*)(dst + q * 8 + 4) = v1;
            }
        }
    }
}

// ---------------------------------------------------------------------------
extern "C" void kernel_launch(void* const* d_in, const int* in_sizes, int n_in,
                              void* d_out, int out_size) {
    const float* keys   = (const float*)d_in[0];
    const float* values = (const float*)d_in[1];
    const float* Pw1    = (const float*)d_in[2];
    const float* Pb1    = (const float*)d_in[3];
    const float* Pw2    = (const float*)d_in[4];
    const float* Pb2    = (const float*)d_in[5];

    CompParams P;
    P.keys = keys; P.values = values;
    for (int l = 0; l < 4; l++) {
        P.w1[l] = (const float*)d_in[6 + l * 4 + 0];
        P.b1[l] = (const float*)d_in[6 + l * 4 + 1];
        P.w2[l] = (const float*)d_in[6 + l * 4 + 2];
        P.b2[l] = (const float*)d_in[6 + l * 4 + 3];
    }
    P.out = (float*)d_out;

    cudaFuncSetAttribute(predictor_mma, cudaFuncAttributeMaxDynamicSharedMemorySize, SMEM_HI);
    cudaFuncSetAttribute(stageA_mma,    cudaFuncAttributeMaxDynamicSharedMemorySize, SMEM_FULL);
    cudaFuncSetAttribute(stageB_mma,    cudaFuncAttributeMaxDynamicSharedMemorySize, SMEM_FULL);

    zero_kernel<<<(TOK_TOTAL * NLEV + 255) / 256, 256>>>();

    splitX_kernel<<<TOK_TOTAL * (HD / 4) / 256, 256>>>(keys, values);

    dim3 wgrid(256, 4);
    prep_kernel<<<wgrid, 256>>>(P, Pw1);

    dim3 pgrid(8, 512);
    predictor_mma<<<pgrid, 256, SMEM_HI>>>(Pb1, Pw2);

    detect_kernel<<<TOK_TOTAL / 256, 256>>>(Pb2);
    refine_kernel<<<MAX_AMB * 4, 128>>>(keys, values, Pw1, Pb1, Pw2);
    argmax_kernel<<<TOK_TOTAL / 256, 256>>>(Pb2);

    dim3 cgrid(8, 512, 4);
    stageA_mma<<<cgrid, 256, SMEM_FULL>>>(P);
    stageB_mma<<<cgrid, 256, SMEM_FULL>>>(P);
}